// round 1
// baseline (speedup 1.0000x reference)
#include <cuda_runtime.h>
#include <math.h>
#include <stdint.h>

// Problem constants
#define BB 2
#define TT 2048
#define CC 1024
#define HH 16
#define HS 64
#define MM (BB*TT)          // 4096 rows
#define EPS 1e-5f

// ---------------- scratch (device globals; no runtime allocation) ----------
__device__ float g_h   [MM*CC];        // LN output (reused for LN2)
__device__ float g_x1  [MM*CC];        // after attention residual
__device__ float g_attn[MM*CC];        // attention output (head-concat)
__device__ float g_qkv [MM*3*CC];      // packed q|k|v, row stride 3072
__device__ float g_wqkv[CC*3*CC];      // packed qkv weight [1024,3072]
__device__ float g_bqkv[3*CC];
__device__ float g_mid [MM*4*CC];      // FFN hidden
__device__ float g_mean[BB*CC];
__device__ float g_inv [BB*CC];

// ---------------- LayerNorm over axis=1 (sequence axis) --------------------
// stats per (b, c): mean over T, unbiased var, inv = 1/(sqrt(var)+eps)
__global__ void ln_stats(const float* __restrict__ x,
                         float* __restrict__ mean, float* __restrict__ inv)
{
    int c = blockIdx.x * 32 + threadIdx.x;
    int b = blockIdx.y;
    float s = 0.f, ss = 0.f;
    for (int t = threadIdx.y; t < TT; t += 8) {
        float v = x[((size_t)b*TT + t)*CC + c];
        s += v; ss += v*v;
    }
    __shared__ float sh_s[8][32];
    __shared__ float sh_q[8][32];
    sh_s[threadIdx.y][threadIdx.x] = s;
    sh_q[threadIdx.y][threadIdx.x] = ss;
    __syncthreads();
    if (threadIdx.y == 0) {
        #pragma unroll
        for (int i = 1; i < 8; i++) { s += sh_s[i][threadIdx.x]; ss += sh_q[i][threadIdx.x]; }
        float mu  = s / (float)TT;
        float var = (ss - s*mu) / (float)(TT - 1);   // unbiased
        mean[b*CC + c] = mu;
        inv [b*CC + c] = 1.f / (sqrtf(var) + EPS);   // eps OUTSIDE sqrt
    }
}

__global__ void ln_apply(const float* __restrict__ x,
                         const float* __restrict__ mean, const float* __restrict__ inv,
                         const float* __restrict__ gamma, const float* __restrict__ beta,
                         float* __restrict__ y)
{
    int idx = blockIdx.x * blockDim.x + threadIdx.x;
    if (idx >= MM*CC) return;
    int c  = idx & (CC-1);
    int bt = idx >> 10;           // /CC
    int b  = bt >> 11;            // /TT
    y[idx] = gamma[c] * ((x[idx] - mean[b*CC + c]) * inv[b*CC + c]) + beta[c];
}

// ---------------- pack Wq/Wk/Wv [H,C,HS] -> [C, 3C] ------------------------
__global__ void pack_qkv(const float* __restrict__ Wq, const float* __restrict__ Wk,
                         const float* __restrict__ Wv,
                         const float* __restrict__ bq, const float* __restrict__ bk,
                         const float* __restrict__ bv,
                         float* __restrict__ W, float* __restrict__ bias)
{
    const int total = CC * 3 * CC;
    for (int idx = blockIdx.x * blockDim.x + threadIdx.x; idx < total;
         idx += gridDim.x * blockDim.x) {
        int k  = idx / (3*CC);
        int nn = idx % (3*CC);
        int sel = nn / CC;
        int r   = nn % CC;
        int h = r / HS, d = r % HS;
        const float* src = (sel == 0) ? Wq : (sel == 1) ? Wk : Wv;
        W[idx] = src[((size_t)h*CC + k)*HS + d];
        if (idx < 3*CC) {
            const float* bs = (idx < CC) ? bq : (idx < 2*CC) ? bk : bv;
            bias[idx] = bs[idx % CC];
        }
    }
}

// ---------------- tiled fp32 SGEMM: C = A[M,K] @ B[K,N] + bias (+relu)(+res)
template<bool RELU, bool RES>
__global__ void __launch_bounds__(256) sgemm_k(
    const float* __restrict__ A, const float* __restrict__ Bm,
    const float* __restrict__ bias, const float* __restrict__ Rm,
    float* __restrict__ Cm, int M, int N, int K)
{
    __shared__ float As[128][16];
    __shared__ float Bs[16][128];
    const int tid = threadIdx.x;
    const int tx = tid & 15, ty = tid >> 4;
    const int rowBase = blockIdx.y * 128;
    const int colBase = blockIdx.x * 128;

    float acc[8][8];
    #pragma unroll
    for (int i = 0; i < 8; i++)
        #pragma unroll
        for (int j = 0; j < 8; j++) acc[i][j] = 0.f;

    const int aRow = tid >> 2;          // 0..63
    const int aCol = (tid & 3) * 4;     // 0,4,8,12
    const int bRow = tid >> 5;          // 0..7
    const int bCol = (tid & 31) * 4;    // 0..124

    const float* Aptr = A + (size_t)rowBase * K;
    const float* Bptr = Bm + colBase;

    for (int k0 = 0; k0 < K; k0 += 16) {
        #pragma unroll
        for (int p = 0; p < 2; p++) {
            int r = aRow + p*64;
            float4 v = *(const float4*)(Aptr + (size_t)r*K + k0 + aCol);
            *(float4*)&As[r][aCol] = v;
        }
        #pragma unroll
        for (int p = 0; p < 2; p++) {
            int r = bRow + p*8;
            float4 v = *(const float4*)(Bptr + (size_t)(k0 + r)*N + bCol);
            *(float4*)&Bs[r][bCol] = v;
        }
        __syncthreads();
        #pragma unroll
        for (int kk = 0; kk < 16; kk++) {
            float a[8], b[8];
            #pragma unroll
            for (int i = 0; i < 8; i++) a[i] = As[ty*8 + i][kk];
            #pragma unroll
            for (int j = 0; j < 8; j++) b[j] = Bs[kk][tx*8 + j];
            #pragma unroll
            for (int i = 0; i < 8; i++)
                #pragma unroll
                for (int j = 0; j < 8; j++)
                    acc[i][j] += a[i] * b[j];
        }
        __syncthreads();
    }

    #pragma unroll
    for (int i = 0; i < 8; i++) {
        int row = rowBase + ty*8 + i;
        #pragma unroll
        for (int j = 0; j < 8; j++) {
            int col = colBase + tx*8 + j;
            float v = acc[i][j] + bias[col];
            if (RELU) v = fmaxf(v, 0.f);
            if (RES)  v += Rm[(size_t)row*N + col];
            Cm[(size_t)row*N + col] = v;
        }
    }
}

// ---------------- flash attention (fp32, non-causal) -----------------------
// grid (T/64, H, B), 64 threads; each thread owns one query row.
__global__ void __launch_bounds__(64) flash_attn(const float* __restrict__ qkv,
                                                 float* __restrict__ out)
{
    __shared__ float Ks[64][64];
    __shared__ float Vs[64][64];
    __shared__ float Ssm[64][64];   // Ssm[j][thread]
    const int tidx = threadIdx.x;
    const int t = blockIdx.x * 64 + tidx;
    const int h = blockIdx.y, b = blockIdx.z;
    const float scale = 0.125f;     // HS^-0.5

    float q[64], o[64];
    const float* qrow = qkv + ((size_t)(b*TT + t))*(3*CC) + h*HS;
    #pragma unroll
    for (int d = 0; d < 64; d += 4) {
        float4 v = *(const float4*)(qrow + d);
        q[d]=v.x*scale; q[d+1]=v.y*scale; q[d+2]=v.z*scale; q[d+3]=v.w*scale;
    }
    #pragma unroll
    for (int d = 0; d < 64; d++) o[d] = 0.f;
    float m = -1e30f, l = 0.f;

    for (int s0 = 0; s0 < TT; s0 += 64) {
        __syncthreads();
        // load K,V tiles: each thread loads one key/value row
        const float* krow = qkv + ((size_t)(b*TT + s0 + tidx))*(3*CC) + CC   + h*HS;
        const float* vrow = qkv + ((size_t)(b*TT + s0 + tidx))*(3*CC) + 2*CC + h*HS;
        #pragma unroll
        for (int d = 0; d < 64; d += 4) {
            *(float4*)&Ks[tidx][d] = *(const float4*)(krow + d);
            *(float4*)&Vs[tidx][d] = *(const float4*)(vrow + d);
        }
        __syncthreads();

        // phase 1: scores for this thread's query vs 64 keys
        float tmax = -1e30f;
        #pragma unroll 4
        for (int j = 0; j < 64; j++) {
            float a0=0.f, a1=0.f, a2=0.f, a3=0.f;
            #pragma unroll
            for (int d = 0; d < 64; d += 4) {
                float4 k4 = *(const float4*)&Ks[j][d];
                a0 += q[d]  *k4.x; a1 += q[d+1]*k4.y;
                a2 += q[d+2]*k4.z; a3 += q[d+3]*k4.w;
            }
            float s = (a0+a1) + (a2+a3);
            Ssm[j][tidx] = s;
            tmax = fmaxf(tmax, s);
        }

        // phase 2: online softmax update
        float newm = fmaxf(m, tmax);
        float f = __expf(m - newm);
        l *= f;
        #pragma unroll
        for (int d = 0; d < 64; d++) o[d] *= f;
        #pragma unroll 2
        for (int j = 0; j < 64; j++) {
            float p = __expf(Ssm[j][tidx] - newm);
            l += p;
            #pragma unroll
            for (int d = 0; d < 64; d += 4) {
                float4 v4 = *(const float4*)&Vs[j][d];
                o[d]   += p*v4.x; o[d+1] += p*v4.y;
                o[d+2] += p*v4.z; o[d+3] += p*v4.w;
            }
        }
        m = newm;
    }

    float invl = 1.f / l;
    float* orow = out + ((size_t)(b*TT + t))*CC + h*HS;   // head-concat layout
    #pragma unroll
    for (int d = 0; d < 64; d += 4) {
        float4 v; v.x=o[d]*invl; v.y=o[d+1]*invl; v.z=o[d+2]*invl; v.w=o[d+3]*invl;
        *(float4*)(orow + d) = v;
    }
}

// ---------------- launch -----------------------------------------------
extern "C" void kernel_launch(void* const* d_in, const int* in_sizes, int n_in,
                              void* d_out, int out_size)
{
    const float* x      = (const float*)d_in[0];
    const float* Wq     = (const float*)d_in[1];
    const float* bq     = (const float*)d_in[2];
    const float* Wk     = (const float*)d_in[3];
    const float* bk     = (const float*)d_in[4];
    const float* Wv     = (const float*)d_in[5];
    const float* bv     = (const float*)d_in[6];
    const float* Wo     = (const float*)d_in[7];
    const float* bo     = (const float*)d_in[8];
    const float* W1     = (const float*)d_in[9];
    const float* b1     = (const float*)d_in[10];
    const float* W2     = (const float*)d_in[11];
    const float* b2     = (const float*)d_in[12];
    const float* gamma1 = (const float*)d_in[13];
    const float* beta1  = (const float*)d_in[14];
    const float* gamma2 = (const float*)d_in[15];
    const float* beta2  = (const float*)d_in[16];
    float* out = (float*)d_out;

    float *p_h, *p_x1, *p_attn, *p_qkv, *p_wqkv, *p_bqkv, *p_mid, *p_mean, *p_inv;
    cudaGetSymbolAddress((void**)&p_h,    g_h);
    cudaGetSymbolAddress((void**)&p_x1,   g_x1);
    cudaGetSymbolAddress((void**)&p_attn, g_attn);
    cudaGetSymbolAddress((void**)&p_qkv,  g_qkv);
    cudaGetSymbolAddress((void**)&p_wqkv, g_wqkv);
    cudaGetSymbolAddress((void**)&p_bqkv, g_bqkv);
    cudaGetSymbolAddress((void**)&p_mid,  g_mid);
    cudaGetSymbolAddress((void**)&p_mean, g_mean);
    cudaGetSymbolAddress((void**)&p_inv,  g_inv);

    dim3 lnb(32, 8);
    dim3 lng(CC/32, BB);
    const int elemBlocks = (MM*CC + 255)/256;

    // 1) LN1
    ln_stats<<<lng, lnb>>>(x, p_mean, p_inv);
    ln_apply<<<elemBlocks, 256>>>(x, p_mean, p_inv, gamma1, beta1, p_h);

    // 2) pack QKV weights + fused QKV GEMM -> g_qkv [4096, 3072]
    pack_qkv<<<4096, 256>>>(Wq, Wk, Wv, bq, bk, bv, p_wqkv, p_bqkv);
    sgemm_k<false,false><<<dim3(3*CC/128, MM/128), 256>>>(p_h, p_wqkv, p_bqkv, nullptr,
                                                          p_qkv, MM, 3*CC, CC);

    // 3) flash attention -> g_attn [4096, 1024] (head-concat order)
    flash_attn<<<dim3(TT/64, HH, BB), 64>>>(p_qkv, p_attn);

    // 4) output projection + residual -> g_x1
    sgemm_k<false,true><<<dim3(CC/128, MM/128), 256>>>(p_attn, Wo, bo, x,
                                                       p_x1, MM, CC, CC);

    // 5) LN2
    ln_stats<<<lng, lnb>>>(p_x1, p_mean, p_inv);
    ln_apply<<<elemBlocks, 256>>>(p_x1, p_mean, p_inv, gamma2, beta2, p_h);

    // 6) FFN: relu(h @ W1 + b1) @ W2 + b2 + residual -> out
    sgemm_k<true,false><<<dim3(4*CC/128, MM/128), 256>>>(p_h, W1, b1, nullptr,
                                                         p_mid, MM, 4*CC, CC);
    sgemm_k<false,true><<<dim3(CC/128, MM/128), 256>>>(p_mid, W2, b2, p_x1,
                                                       out, MM, CC, 4*CC);
}

// round 2
// speedup vs baseline: 2.6683x; 2.6683x over previous
#include <cuda_runtime.h>
#include <math.h>
#include <stdint.h>

// Problem constants
#define BB 2
#define TT 2048
#define CC 1024
#define HH 16
#define HS 64
#define MM (BB*TT)          // 4096 rows
#define EPS 1e-5f

// ---------------- scratch (device globals; no runtime allocation) ----------
__device__ float g_h   [MM*CC];        // LN output (reused for LN2)
__device__ float g_x1  [MM*CC];        // after attention residual
__device__ float g_attn[MM*CC];        // attention output (head-concat)
__device__ float g_qkv [MM*3*CC];      // packed q|k|v, row stride 3072
__device__ float g_wqkv[CC*3*CC];      // packed qkv weight [1024,3072]
__device__ float g_bqkv[3*CC];
__device__ float g_mid [MM*4*CC];      // FFN hidden
__device__ float g_mean[BB*CC];
__device__ float g_inv [BB*CC];

// ---------------- helpers ---------------------------------------------------
__device__ __forceinline__ uint32_t f2tf32(float f) {
    uint32_t r;
    asm("cvt.rna.tf32.f32 %0, %1;" : "=r"(r) : "f"(f));
    return r;
}

__device__ __forceinline__ void mma_tf32(float c[4], const uint32_t a[4],
                                         uint32_t b0, uint32_t b1) {
    asm("mma.sync.aligned.m16n8k8.row.col.f32.tf32.tf32.f32 "
        "{%0,%1,%2,%3},{%4,%5,%6,%7},{%8,%9},{%0,%1,%2,%3};"
        : "+f"(c[0]), "+f"(c[1]), "+f"(c[2]), "+f"(c[3])
        : "r"(a[0]), "r"(a[1]), "r"(a[2]), "r"(a[3]), "r"(b0), "r"(b1));
}

// ---------------- LayerNorm over axis=1 (sequence axis) --------------------
__global__ void ln_stats(const float* __restrict__ x,
                         float* __restrict__ mean, float* __restrict__ inv)
{
    int c = blockIdx.x * 32 + threadIdx.x;
    int b = blockIdx.y;
    float s = 0.f, ss = 0.f;
    for (int t = threadIdx.y; t < TT; t += 8) {
        float v = x[((size_t)b*TT + t)*CC + c];
        s += v; ss += v*v;
    }
    __shared__ float sh_s[8][32];
    __shared__ float sh_q[8][32];
    sh_s[threadIdx.y][threadIdx.x] = s;
    sh_q[threadIdx.y][threadIdx.x] = ss;
    __syncthreads();
    if (threadIdx.y == 0) {
        #pragma unroll
        for (int i = 1; i < 8; i++) { s += sh_s[i][threadIdx.x]; ss += sh_q[i][threadIdx.x]; }
        float mu  = s / (float)TT;
        float var = (ss - s*mu) / (float)(TT - 1);   // unbiased
        mean[b*CC + c] = mu;
        inv [b*CC + c] = 1.f / (sqrtf(var) + EPS);   // eps OUTSIDE sqrt
    }
}

__global__ void ln_apply(const float* __restrict__ x,
                         const float* __restrict__ mean, const float* __restrict__ inv,
                         const float* __restrict__ gamma, const float* __restrict__ beta,
                         float* __restrict__ y)
{
    int idx = blockIdx.x * blockDim.x + threadIdx.x;
    if (idx >= MM*CC) return;
    int c  = idx & (CC-1);
    int bt = idx >> 10;
    int b  = bt >> 11;
    y[idx] = gamma[c] * ((x[idx] - mean[b*CC + c]) * inv[b*CC + c]) + beta[c];
}

// ---------------- pack Wq/Wk/Wv [H,C,HS] -> [C, 3C] ------------------------
__global__ void pack_qkv(const float* __restrict__ Wq, const float* __restrict__ Wk,
                         const float* __restrict__ Wv,
                         const float* __restrict__ bq, const float* __restrict__ bk,
                         const float* __restrict__ bv,
                         float* __restrict__ W, float* __restrict__ bias)
{
    const int total = CC * 3 * CC;
    for (int idx = blockIdx.x * blockDim.x + threadIdx.x; idx < total;
         idx += gridDim.x * blockDim.x) {
        int k  = idx / (3*CC);
        int nn = idx % (3*CC);
        int sel = nn / CC;
        int r   = nn % CC;
        int h = r / HS, d = r % HS;
        const float* src = (sel == 0) ? Wq : (sel == 1) ? Wk : Wv;
        W[idx] = src[((size_t)h*CC + k)*HS + d];
        if (idx < 3*CC) {
            const float* bs = (idx < CC) ? bq : (idx < 2*CC) ? bk : bv;
            bias[idx] = bs[idx % CC];
        }
    }
}

// ---------------- TF32 MMA GEMM: C = A[M,K] @ B[K,N] + bias (+relu)(+res) --
// 128x128 block tile, BK=16, 8 warps (warp tile 32x64), m16n8k8 tf32 MMA.
template<bool RELU, bool RES>
__global__ void __launch_bounds__(256) mma_gemm(
    const float* __restrict__ A, const float* __restrict__ Bm,
    const float* __restrict__ bias, const float* __restrict__ Rm,
    float* __restrict__ Cm, int M, int N, int K)
{
    __shared__ uint32_t As[16][136];   // [k][m], tf32 bits; stride 136 -> conflict-free
    __shared__ uint32_t Bs[16][136];   // [k][n]

    const int tid  = threadIdx.x;
    const int lane = tid & 31;
    const int warp = tid >> 5;
    const int wm = warp & 3;           // 4 warps down  (4*32 = 128 rows)
    const int wn = warp >> 2;          // 2 warps across (2*64 = 128 cols)
    const int r = lane >> 2;           // groupID
    const int c = lane & 3;            // thread-in-group
    const int rowBase = blockIdx.y * 128;
    const int colBase = blockIdx.x * 128;

    float acc[2][8][4];
    #pragma unroll
    for (int mt = 0; mt < 2; mt++)
        #pragma unroll
        for (int nt = 0; nt < 8; nt++)
            #pragma unroll
            for (int i = 0; i < 4; i++) acc[mt][nt][i] = 0.f;

    // staging maps
    const int am = tid >> 1;           // 0..127
    const int ak = (tid & 1) * 8;      // 0 or 8
    const int bk = tid >> 4;           // 0..15
    const int bn = (tid & 15) * 8;     // 0..120

    const float* Arow = A + (size_t)(rowBase + am) * K + ak;

    for (int k0 = 0; k0 < K; k0 += 16) {
        // stage A (transposed into [k][m]) with tf32 conversion
        float4 a0 = *(const float4*)(Arow + k0);
        float4 a1 = *(const float4*)(Arow + k0 + 4);
        As[ak+0][am] = f2tf32(a0.x); As[ak+1][am] = f2tf32(a0.y);
        As[ak+2][am] = f2tf32(a0.z); As[ak+3][am] = f2tf32(a0.w);
        As[ak+4][am] = f2tf32(a1.x); As[ak+5][am] = f2tf32(a1.y);
        As[ak+6][am] = f2tf32(a1.z); As[ak+7][am] = f2tf32(a1.w);
        // stage B ([k][n]) with tf32 conversion
        const float* Bp = Bm + (size_t)(k0 + bk) * N + colBase + bn;
        float4 b0 = *(const float4*)(Bp);
        float4 b1 = *(const float4*)(Bp + 4);
        Bs[bk][bn+0] = f2tf32(b0.x); Bs[bk][bn+1] = f2tf32(b0.y);
        Bs[bk][bn+2] = f2tf32(b0.z); Bs[bk][bn+3] = f2tf32(b0.w);
        Bs[bk][bn+4] = f2tf32(b1.x); Bs[bk][bn+5] = f2tf32(b1.y);
        Bs[bk][bn+6] = f2tf32(b1.z); Bs[bk][bn+7] = f2tf32(b1.w);
        __syncthreads();

        #pragma unroll
        for (int ks = 0; ks < 16; ks += 8) {
            uint32_t af[2][4];
            #pragma unroll
            for (int mt = 0; mt < 2; mt++) {
                int m = wm*32 + mt*16;
                af[mt][0] = As[ks+c  ][m+r  ];
                af[mt][1] = As[ks+c  ][m+r+8];
                af[mt][2] = As[ks+c+4][m+r  ];
                af[mt][3] = As[ks+c+4][m+r+8];
            }
            #pragma unroll
            for (int nt = 0; nt < 8; nt++) {
                int n = wn*64 + nt*8;
                uint32_t b0 = Bs[ks+c  ][n+r];
                uint32_t b1 = Bs[ks+c+4][n+r];
                mma_tf32(acc[0][nt], af[0], b0, b1);
                mma_tf32(acc[1][nt], af[1], b0, b1);
            }
        }
        __syncthreads();
    }

    // epilogue
    #pragma unroll
    for (int mt = 0; mt < 2; mt++) {
        #pragma unroll
        for (int nt = 0; nt < 8; nt++) {
            int row0 = rowBase + wm*32 + mt*16 + r;
            int col  = colBase + wn*64 + nt*8 + 2*c;
            float bi0 = bias[col], bi1 = bias[col+1];
            float v0 = acc[mt][nt][0] + bi0;
            float v1 = acc[mt][nt][1] + bi1;
            float v2 = acc[mt][nt][2] + bi0;
            float v3 = acc[mt][nt][3] + bi1;
            if (RELU) { v0=fmaxf(v0,0.f); v1=fmaxf(v1,0.f); v2=fmaxf(v2,0.f); v3=fmaxf(v3,0.f); }
            if (RES) {
                const float2 r0 = *(const float2*)(Rm + (size_t)row0*N + col);
                const float2 r1 = *(const float2*)(Rm + (size_t)(row0+8)*N + col);
                v0 += r0.x; v1 += r0.y; v2 += r1.x; v3 += r1.y;
            }
            *(float2*)(Cm + (size_t)row0*N + col)     = make_float2(v0, v1);
            *(float2*)(Cm + (size_t)(row0+8)*N + col) = make_float2(v2, v3);
        }
    }
}

// ---------------- flash attention (tf32 MMA, non-causal) -------------------
// grid (T/64, H, B); 128 threads = 4 warps; each warp owns 16 query rows.
__global__ void __launch_bounds__(128) flash_mma(const float* __restrict__ qkv,
                                                 float* __restrict__ out)
{
    __shared__ uint32_t Kt[64][72];   // [d][key]  (K transposed), tf32 bits
    __shared__ uint32_t Vs[64][72];   // [key][d]
    __shared__ uint32_t Ps[64][72];   // [qrow][key]  probabilities, tf32 bits

    const int tid  = threadIdx.x;
    const int lane = tid & 31;
    const int warp = tid >> 5;
    const int r = lane >> 2;
    const int c = lane & 3;
    const int b = blockIdx.z, h = blockIdx.y;
    const int q0 = blockIdx.x * 64;
    const float scale = 0.125f;       // HS^-0.5

    // preload Q fragments (registers, one-time), scaled + tf32
    uint32_t qf[8][4];
    {
        const int qr0 = b*TT + q0 + warp*16 + r;
        const float* qp = qkv + (size_t)qr0 * (3*CC) + h*HS;
        const float* qp8 = qp + (size_t)8 * (3*CC);
        #pragma unroll
        for (int ks = 0; ks < 8; ks++) {
            qf[ks][0] = f2tf32(qp [ks*8 + c    ] * scale);
            qf[ks][1] = f2tf32(qp8[ks*8 + c    ] * scale);
            qf[ks][2] = f2tf32(qp [ks*8 + c + 4] * scale);
            qf[ks][3] = f2tf32(qp8[ks*8 + c + 4] * scale);
        }
    }

    float oacc[8][4];
    #pragma unroll
    for (int nt = 0; nt < 8; nt++)
        #pragma unroll
        for (int i = 0; i < 4; i++) oacc[nt][i] = 0.f;
    float m0 = -1e30f, m1 = -1e30f, l0 = 0.f, l1 = 0.f;

    // staging map: thread -> (key, 32-wide d chunk)
    const int skey = tid >> 1;
    const int sdg  = (tid & 1) * 32;

    for (int s0 = 0; s0 < TT; s0 += 64) {
        __syncthreads();
        // stage K (transposed) and V tiles
        const float* kr = qkv + (size_t)(b*TT + s0 + skey)*(3*CC) +   CC + h*HS + sdg;
        const float* vr = qkv + (size_t)(b*TT + s0 + skey)*(3*CC) + 2*CC + h*HS + sdg;
        #pragma unroll
        for (int j = 0; j < 8; j++) {
            float4 kv = *(const float4*)(kr + j*4);
            Kt[sdg + j*4 + 0][skey] = f2tf32(kv.x);
            Kt[sdg + j*4 + 1][skey] = f2tf32(kv.y);
            Kt[sdg + j*4 + 2][skey] = f2tf32(kv.z);
            Kt[sdg + j*4 + 3][skey] = f2tf32(kv.w);
            float4 vv = *(const float4*)(vr + j*4);
            uint4 u;
            u.x = f2tf32(vv.x); u.y = f2tf32(vv.y);
            u.z = f2tf32(vv.z); u.w = f2tf32(vv.w);
            *(uint4*)&Vs[skey][sdg + j*4] = u;
        }
        __syncthreads();

        // S = Q K^T  (warp: 16 x 64)
        float sa[8][4];
        #pragma unroll
        for (int nt = 0; nt < 8; nt++)
            #pragma unroll
            for (int i = 0; i < 4; i++) sa[nt][i] = 0.f;
        #pragma unroll
        for (int ks = 0; ks < 8; ks++) {
            #pragma unroll
            for (int nt = 0; nt < 8; nt++) {
                uint32_t b0 = Kt[ks*8 + c    ][nt*8 + r];
                uint32_t b1 = Kt[ks*8 + c + 4][nt*8 + r];
                mma_tf32(sa[nt], qf[ks], b0, b1);
            }
        }

        // online softmax (rows r and r+8 of this warp's 16-row slab)
        float mx0 = -1e30f, mx1 = -1e30f;
        #pragma unroll
        for (int nt = 0; nt < 8; nt++) {
            mx0 = fmaxf(mx0, fmaxf(sa[nt][0], sa[nt][1]));
            mx1 = fmaxf(mx1, fmaxf(sa[nt][2], sa[nt][3]));
        }
        mx0 = fmaxf(mx0, __shfl_xor_sync(0xffffffff, mx0, 1));
        mx0 = fmaxf(mx0, __shfl_xor_sync(0xffffffff, mx0, 2));
        mx1 = fmaxf(mx1, __shfl_xor_sync(0xffffffff, mx1, 1));
        mx1 = fmaxf(mx1, __shfl_xor_sync(0xffffffff, mx1, 2));
        float mn0 = fmaxf(m0, mx0), mn1 = fmaxf(m1, mx1);
        float f0 = __expf(m0 - mn0), f1 = __expf(m1 - mn1);
        m0 = mn0; m1 = mn1;

        float ps0 = 0.f, ps1 = 0.f;
        const int prow = warp*16 + r;
        #pragma unroll
        for (int nt = 0; nt < 8; nt++) {
            float p0 = __expf(sa[nt][0] - mn0);
            float p1 = __expf(sa[nt][1] - mn0);
            float p2 = __expf(sa[nt][2] - mn1);
            float p3 = __expf(sa[nt][3] - mn1);
            ps0 += p0 + p1; ps1 += p2 + p3;
            uint2 w0; w0.x = f2tf32(p0); w0.y = f2tf32(p1);
            uint2 w1; w1.x = f2tf32(p2); w1.y = f2tf32(p3);
            *(uint2*)&Ps[prow    ][nt*8 + 2*c] = w0;
            *(uint2*)&Ps[prow + 8][nt*8 + 2*c] = w1;
        }
        ps0 += __shfl_xor_sync(0xffffffff, ps0, 1);
        ps0 += __shfl_xor_sync(0xffffffff, ps0, 2);
        ps1 += __shfl_xor_sync(0xffffffff, ps1, 1);
        ps1 += __shfl_xor_sync(0xffffffff, ps1, 2);
        l0 = l0 * f0 + ps0;
        l1 = l1 * f1 + ps1;

        // rescale O
        #pragma unroll
        for (int nt = 0; nt < 8; nt++) {
            oacc[nt][0] *= f0; oacc[nt][1] *= f0;
            oacc[nt][2] *= f1; oacc[nt][3] *= f1;
        }
        __syncwarp();

        // O += P V  (warp: 16 x 64, k = 64 keys)
        #pragma unroll
        for (int ks = 0; ks < 8; ks++) {
            uint32_t af[4];
            af[0] = Ps[prow    ][ks*8 + c    ];
            af[1] = Ps[prow + 8][ks*8 + c    ];
            af[2] = Ps[prow    ][ks*8 + c + 4];
            af[3] = Ps[prow + 8][ks*8 + c + 4];
            #pragma unroll
            for (int nt = 0; nt < 8; nt++) {
                uint32_t b0 = Vs[ks*8 + c    ][nt*8 + r];
                uint32_t b1 = Vs[ks*8 + c + 4][nt*8 + r];
                mma_tf32(oacc[nt], af, b0, b1);
            }
        }
        __syncwarp();
    }

    // write out (head-concat layout)
    float il0 = 1.f / l0, il1 = 1.f / l1;
    const int grow = b*TT + q0 + warp*16 + r;
    float* op0 = out + (size_t)grow * CC + h*HS;
    float* op1 = op0 + (size_t)8 * CC;
    #pragma unroll
    for (int nt = 0; nt < 8; nt++) {
        int col = nt*8 + 2*c;
        *(float2*)(op0 + col) = make_float2(oacc[nt][0]*il0, oacc[nt][1]*il0);
        *(float2*)(op1 + col) = make_float2(oacc[nt][2]*il1, oacc[nt][3]*il1);
    }
}

// ---------------- launch -----------------------------------------------
extern "C" void kernel_launch(void* const* d_in, const int* in_sizes, int n_in,
                              void* d_out, int out_size)
{
    const float* x      = (const float*)d_in[0];
    const float* Wq     = (const float*)d_in[1];
    const float* bq     = (const float*)d_in[2];
    const float* Wk     = (const float*)d_in[3];
    const float* bk     = (const float*)d_in[4];
    const float* Wv     = (const float*)d_in[5];
    const float* bv     = (const float*)d_in[6];
    const float* Wo     = (const float*)d_in[7];
    const float* bo     = (const float*)d_in[8];
    const float* W1     = (const float*)d_in[9];
    const float* b1     = (const float*)d_in[10];
    const float* W2     = (const float*)d_in[11];
    const float* b2     = (const float*)d_in[12];
    const float* gamma1 = (const float*)d_in[13];
    const float* beta1  = (const float*)d_in[14];
    const float* gamma2 = (const float*)d_in[15];
    const float* beta2  = (const float*)d_in[16];
    float* out = (float*)d_out;

    float *p_h, *p_x1, *p_attn, *p_qkv, *p_wqkv, *p_bqkv, *p_mid, *p_mean, *p_inv;
    cudaGetSymbolAddress((void**)&p_h,    g_h);
    cudaGetSymbolAddress((void**)&p_x1,   g_x1);
    cudaGetSymbolAddress((void**)&p_attn, g_attn);
    cudaGetSymbolAddress((void**)&p_qkv,  g_qkv);
    cudaGetSymbolAddress((void**)&p_wqkv, g_wqkv);
    cudaGetSymbolAddress((void**)&p_bqkv, g_bqkv);
    cudaGetSymbolAddress((void**)&p_mid,  g_mid);
    cudaGetSymbolAddress((void**)&p_mean, g_mean);
    cudaGetSymbolAddress((void**)&p_inv,  g_inv);

    dim3 lnb(32, 8);
    dim3 lng(CC/32, BB);
    const int elemBlocks = (MM*CC + 255)/256;

    // 1) LN1
    ln_stats<<<lng, lnb>>>(x, p_mean, p_inv);
    ln_apply<<<elemBlocks, 256>>>(x, p_mean, p_inv, gamma1, beta1, p_h);

    // 2) pack QKV weights + fused QKV GEMM -> g_qkv [4096, 3072]
    pack_qkv<<<4096, 256>>>(Wq, Wk, Wv, bq, bk, bv, p_wqkv, p_bqkv);
    mma_gemm<false,false><<<dim3(3*CC/128, MM/128), 256>>>(p_h, p_wqkv, p_bqkv, nullptr,
                                                           p_qkv, MM, 3*CC, CC);

    // 3) flash attention -> g_attn [4096, 1024] (head-concat order)
    flash_mma<<<dim3(TT/64, HH, BB), 128>>>(p_qkv, p_attn);

    // 4) output projection + residual -> g_x1
    mma_gemm<false,true><<<dim3(CC/128, MM/128), 256>>>(p_attn, Wo, bo, x,
                                                        p_x1, MM, CC, CC);

    // 5) LN2
    ln_stats<<<lng, lnb>>>(p_x1, p_mean, p_inv);
    ln_apply<<<elemBlocks, 256>>>(p_x1, p_mean, p_inv, gamma2, beta2, p_h);

    // 6) FFN: relu(h @ W1 + b1) @ W2 + b2 + residual -> out
    mma_gemm<true,false><<<dim3(4*CC/128, MM/128), 256>>>(p_h, W1, b1, nullptr,
                                                          p_mid, MM, 4*CC, CC);
    mma_gemm<false,true><<<dim3(CC/128, MM/128), 256>>>(p_mid, W2, b2, p_x1,
                                                        out, MM, CC, 4*CC);
}

// round 3
// speedup vs baseline: 3.3025x; 1.2377x over previous
#include <cuda_runtime.h>
#include <math.h>
#include <stdint.h>

// Problem constants
#define BB 2
#define TT 2048
#define CC 1024
#define HH 16
#define HS 64
#define MM (BB*TT)          // 4096 rows
#define EPS 1e-5f

// ---------------- scratch (device globals; no runtime allocation) ----------
__device__ float g_h   [MM*CC];
__device__ float g_x1  [MM*CC];
__device__ float g_attn[MM*CC];
__device__ float g_qkv [MM*3*CC];
__device__ float g_wqkv[CC*3*CC];
__device__ float g_bqkv[3*CC];
__device__ float g_mid [MM*4*CC];
__device__ float g_mean[BB*CC];
__device__ float g_inv [BB*CC];

// ---------------- helpers ---------------------------------------------------
__device__ __forceinline__ uint32_t f2tf32(float f) {
    uint32_t r;
    asm("cvt.rna.tf32.f32 %0, %1;" : "=r"(r) : "f"(f));
    return r;
}

__device__ __forceinline__ void mma_tf32(float c[4], const uint32_t a[4],
                                         uint32_t b0, uint32_t b1) {
    asm("mma.sync.aligned.m16n8k8.row.col.f32.tf32.tf32.f32 "
        "{%0,%1,%2,%3},{%4,%5,%6,%7},{%8,%9},{%0,%1,%2,%3};"
        : "+f"(c[0]), "+f"(c[1]), "+f"(c[2]), "+f"(c[3])
        : "r"(a[0]), "r"(a[1]), "r"(a[2]), "r"(a[3]), "r"(b0), "r"(b1));
}

__device__ __forceinline__ void cp16(void* smem, const void* gmem) {
    uint32_t s = (uint32_t)__cvta_generic_to_shared(smem);
    asm volatile("cp.async.cg.shared.global [%0], [%1], 16;\n" :: "r"(s), "l"(gmem));
}
__device__ __forceinline__ void cp_commit() {
    asm volatile("cp.async.commit_group;\n");
}
template<int N>
__device__ __forceinline__ void cp_wait() {
    asm volatile("cp.async.wait_group %0;\n" :: "n"(N));
}

// ---------------- LayerNorm over axis=1 (sequence axis) --------------------
__global__ void ln_stats(const float* __restrict__ x,
                         float* __restrict__ mean, float* __restrict__ inv)
{
    int c = blockIdx.x * 32 + threadIdx.x;
    int b = blockIdx.y;
    float s = 0.f, ss = 0.f;
    for (int t = threadIdx.y; t < TT; t += 8) {
        float v = x[((size_t)b*TT + t)*CC + c];
        s += v; ss += v*v;
    }
    __shared__ float sh_s[8][32];
    __shared__ float sh_q[8][32];
    sh_s[threadIdx.y][threadIdx.x] = s;
    sh_q[threadIdx.y][threadIdx.x] = ss;
    __syncthreads();
    if (threadIdx.y == 0) {
        #pragma unroll
        for (int i = 1; i < 8; i++) { s += sh_s[i][threadIdx.x]; ss += sh_q[i][threadIdx.x]; }
        float mu  = s / (float)TT;
        float var = (ss - s*mu) / (float)(TT - 1);
        mean[b*CC + c] = mu;
        inv [b*CC + c] = 1.f / (sqrtf(var) + EPS);
    }
}

__global__ void ln_apply(const float* __restrict__ x,
                         const float* __restrict__ mean, const float* __restrict__ inv,
                         const float* __restrict__ gamma, const float* __restrict__ beta,
                         float* __restrict__ y)
{
    int idx = blockIdx.x * blockDim.x + threadIdx.x;
    if (idx >= MM*CC) return;
    int c  = idx & (CC-1);
    int bt = idx >> 10;
    int b  = bt >> 11;
    y[idx] = gamma[c] * ((x[idx] - mean[b*CC + c]) * inv[b*CC + c]) + beta[c];
}

// ---------------- pack Wq/Wk/Wv [H,C,HS] -> [C, 3C] ------------------------
__global__ void pack_qkv(const float* __restrict__ Wq, const float* __restrict__ Wk,
                         const float* __restrict__ Wv,
                         const float* __restrict__ bq, const float* __restrict__ bk,
                         const float* __restrict__ bv,
                         float* __restrict__ W, float* __restrict__ bias)
{
    const int total = CC * 3 * CC;
    for (int idx = blockIdx.x * blockDim.x + threadIdx.x; idx < total;
         idx += gridDim.x * blockDim.x) {
        int k  = idx / (3*CC);
        int nn = idx % (3*CC);
        int sel = nn / CC;
        int r   = nn % CC;
        int h = r / HS, d = r % HS;
        const float* src = (sel == 0) ? Wq : (sel == 1) ? Wk : Wv;
        W[idx] = src[((size_t)h*CC + k)*HS + d];
        if (idx < 3*CC) {
            const float* bs = (idx < CC) ? bq : (idx < 2*CC) ? bk : bv;
            bias[idx] = bs[idx % CC];
        }
    }
}

// ---------------- TF32 MMA GEMM, 2-stage cp.async pipeline -----------------
// 128x128 block tile, BK=16, 8 warps (warp tile 32x64), m16n8k8 tf32 MMA.
template<bool RELU, bool RES>
__global__ void __launch_bounds__(256, 2) mma_gemm(
    const float* __restrict__ A, const float* __restrict__ Bm,
    const float* __restrict__ bias, const float* __restrict__ Rm,
    float* __restrict__ Cm, int M, int N, int K)
{
    __shared__ float As[2][128][20];    // [stage][m][k] fp32, stride 20 (conflict-free)
    __shared__ float Bs[2][16][136];    // [stage][k][n] fp32, stride 136 (conflict-free)

    const int tid  = threadIdx.x;
    const int lane = tid & 31;
    const int warp = tid >> 5;
    const int wm = warp & 3;
    const int wn = warp >> 2;
    const int r = lane >> 2;
    const int c = lane & 3;
    const int rowBase = blockIdx.y * 128;
    const int colBase = blockIdx.x * 128;

    float acc[2][8][4];
    #pragma unroll
    for (int mt = 0; mt < 2; mt++)
        #pragma unroll
        for (int nt = 0; nt < 8; nt++)
            #pragma unroll
            for (int i = 0; i < 4; i++) acc[mt][nt][i] = 0.f;

    // staging maps: 512 16B-chunks each for A and B, 2 per thread
    const int aRow0 = tid >> 1;               // chunks tid, tid+256 -> rows tid>>1? (see below)
    // A: chunk q -> row=q>>2, kcol=(q&3)*4
    // B: chunk q -> krow=q>>5, ncol=(q&31)*4

    const float* Ag = A + (size_t)rowBase * K;
    const float* Bg = Bm + colBase;
    (void)aRow0;

    const int nIter = K >> 4;

    auto stage = [&](int s, int k0) {
        #pragma unroll
        for (int p = 0; p < 2; p++) {
            int q = tid + p*256;
            int row = q >> 2, kc = (q & 3) * 4;
            cp16(&As[s][row][kc], Ag + (size_t)row * K + k0 + kc);
        }
        #pragma unroll
        for (int p = 0; p < 2; p++) {
            int q = tid + p*256;
            int kr = q >> 5, nc = (q & 31) * 4;
            cp16(&Bs[s][kr][nc], Bg + (size_t)(k0 + kr) * N + nc);
        }
        cp_commit();
    };

    stage(0, 0);

    for (int it = 0; it < nIter; it++) {
        const int s = it & 1;
        if (it + 1 < nIter) {
            stage(s ^ 1, (it + 1) << 4);
            cp_wait<1>();
        } else {
            cp_wait<0>();
        }
        __syncthreads();

        #pragma unroll
        for (int ks = 0; ks < 16; ks += 8) {
            uint32_t af[2][4];
            #pragma unroll
            for (int mt = 0; mt < 2; mt++) {
                int m = wm*32 + mt*16;
                af[mt][0] = f2tf32(As[s][m+r  ][ks+c  ]);
                af[mt][1] = f2tf32(As[s][m+r+8][ks+c  ]);
                af[mt][2] = f2tf32(As[s][m+r  ][ks+c+4]);
                af[mt][3] = f2tf32(As[s][m+r+8][ks+c+4]);
            }
            #pragma unroll
            for (int nt = 0; nt < 8; nt++) {
                int n = wn*64 + nt*8;
                uint32_t b0 = f2tf32(Bs[s][ks+c  ][n+r]);
                uint32_t b1 = f2tf32(Bs[s][ks+c+4][n+r]);
                mma_tf32(acc[0][nt], af[0], b0, b1);
                mma_tf32(acc[1][nt], af[1], b0, b1);
            }
        }
        __syncthreads();
    }

    // epilogue
    #pragma unroll
    for (int mt = 0; mt < 2; mt++) {
        #pragma unroll
        for (int nt = 0; nt < 8; nt++) {
            int row0 = rowBase + wm*32 + mt*16 + r;
            int col  = colBase + wn*64 + nt*8 + 2*c;
            float bi0 = bias[col], bi1 = bias[col+1];
            float v0 = acc[mt][nt][0] + bi0;
            float v1 = acc[mt][nt][1] + bi1;
            float v2 = acc[mt][nt][2] + bi0;
            float v3 = acc[mt][nt][3] + bi1;
            if (RELU) { v0=fmaxf(v0,0.f); v1=fmaxf(v1,0.f); v2=fmaxf(v2,0.f); v3=fmaxf(v3,0.f); }
            if (RES) {
                const float2 r0 = *(const float2*)(Rm + (size_t)row0*N + col);
                const float2 r1 = *(const float2*)(Rm + (size_t)(row0+8)*N + col);
                v0 += r0.x; v1 += r0.y; v2 += r1.x; v3 += r1.y;
            }
            *(float2*)(Cm + (size_t)row0*N + col)     = make_float2(v0, v1);
            *(float2*)(Cm + (size_t)(row0+8)*N + col) = make_float2(v2, v3);
        }
    }
}

// ---------------- flash attention (tf32 MMA, non-causal) -------------------
__global__ void __launch_bounds__(128) flash_mma(const float* __restrict__ qkv,
                                                 float* __restrict__ out)
{
    __shared__ uint32_t Kt[64][72];
    __shared__ uint32_t Vs[64][72];
    __shared__ uint32_t Ps[64][72];

    const int tid  = threadIdx.x;
    const int lane = tid & 31;
    const int warp = tid >> 5;
    const int r = lane >> 2;
    const int c = lane & 3;
    const int b = blockIdx.z, h = blockIdx.y;
    const int q0 = blockIdx.x * 64;
    const float scale = 0.125f;

    uint32_t qf[8][4];
    {
        const int qr0 = b*TT + q0 + warp*16 + r;
        const float* qp = qkv + (size_t)qr0 * (3*CC) + h*HS;
        const float* qp8 = qp + (size_t)8 * (3*CC);
        #pragma unroll
        for (int ks = 0; ks < 8; ks++) {
            qf[ks][0] = f2tf32(qp [ks*8 + c    ] * scale);
            qf[ks][1] = f2tf32(qp8[ks*8 + c    ] * scale);
            qf[ks][2] = f2tf32(qp [ks*8 + c + 4] * scale);
            qf[ks][3] = f2tf32(qp8[ks*8 + c + 4] * scale);
        }
    }

    float oacc[8][4];
    #pragma unroll
    for (int nt = 0; nt < 8; nt++)
        #pragma unroll
        for (int i = 0; i < 4; i++) oacc[nt][i] = 0.f;
    float m0 = -1e30f, m1 = -1e30f, l0 = 0.f, l1 = 0.f;

    const int skey = tid >> 1;
    const int sdg  = (tid & 1) * 32;

    for (int s0 = 0; s0 < TT; s0 += 64) {
        __syncthreads();
        const float* kr = qkv + (size_t)(b*TT + s0 + skey)*(3*CC) +   CC + h*HS + sdg;
        const float* vr = qkv + (size_t)(b*TT + s0 + skey)*(3*CC) + 2*CC + h*HS + sdg;
        #pragma unroll
        for (int j = 0; j < 8; j++) {
            float4 kv = *(const float4*)(kr + j*4);
            Kt[sdg + j*4 + 0][skey] = f2tf32(kv.x);
            Kt[sdg + j*4 + 1][skey] = f2tf32(kv.y);
            Kt[sdg + j*4 + 2][skey] = f2tf32(kv.z);
            Kt[sdg + j*4 + 3][skey] = f2tf32(kv.w);
            float4 vv = *(const float4*)(vr + j*4);
            uint4 u;
            u.x = f2tf32(vv.x); u.y = f2tf32(vv.y);
            u.z = f2tf32(vv.z); u.w = f2tf32(vv.w);
            *(uint4*)&Vs[skey][sdg + j*4] = u;
        }
        __syncthreads();

        float sa[8][4];
        #pragma unroll
        for (int nt = 0; nt < 8; nt++)
            #pragma unroll
            for (int i = 0; i < 4; i++) sa[nt][i] = 0.f;
        #pragma unroll
        for (int ks = 0; ks < 8; ks++) {
            #pragma unroll
            for (int nt = 0; nt < 8; nt++) {
                uint32_t b0 = Kt[ks*8 + c    ][nt*8 + r];
                uint32_t b1 = Kt[ks*8 + c + 4][nt*8 + r];
                mma_tf32(sa[nt], qf[ks], b0, b1);
            }
        }

        float mx0 = -1e30f, mx1 = -1e30f;
        #pragma unroll
        for (int nt = 0; nt < 8; nt++) {
            mx0 = fmaxf(mx0, fmaxf(sa[nt][0], sa[nt][1]));
            mx1 = fmaxf(mx1, fmaxf(sa[nt][2], sa[nt][3]));
        }
        mx0 = fmaxf(mx0, __shfl_xor_sync(0xffffffff, mx0, 1));
        mx0 = fmaxf(mx0, __shfl_xor_sync(0xffffffff, mx0, 2));
        mx1 = fmaxf(mx1, __shfl_xor_sync(0xffffffff, mx1, 1));
        mx1 = fmaxf(mx1, __shfl_xor_sync(0xffffffff, mx1, 2));
        float mn0 = fmaxf(m0, mx0), mn1 = fmaxf(m1, mx1);
        float f0 = __expf(m0 - mn0), f1 = __expf(m1 - mn1);
        m0 = mn0; m1 = mn1;

        float ps0 = 0.f, ps1 = 0.f;
        const int prow = warp*16 + r;
        #pragma unroll
        for (int nt = 0; nt < 8; nt++) {
            float p0 = __expf(sa[nt][0] - mn0);
            float p1 = __expf(sa[nt][1] - mn0);
            float p2 = __expf(sa[nt][2] - mn1);
            float p3 = __expf(sa[nt][3] - mn1);
            ps0 += p0 + p1; ps1 += p2 + p3;
            uint2 w0; w0.x = f2tf32(p0); w0.y = f2tf32(p1);
            uint2 w1; w1.x = f2tf32(p2); w1.y = f2tf32(p3);
            *(uint2*)&Ps[prow    ][nt*8 + 2*c] = w0;
            *(uint2*)&Ps[prow + 8][nt*8 + 2*c] = w1;
        }
        ps0 += __shfl_xor_sync(0xffffffff, ps0, 1);
        ps0 += __shfl_xor_sync(0xffffffff, ps0, 2);
        ps1 += __shfl_xor_sync(0xffffffff, ps1, 1);
        ps1 += __shfl_xor_sync(0xffffffff, ps1, 2);
        l0 = l0 * f0 + ps0;
        l1 = l1 * f1 + ps1;

        #pragma unroll
        for (int nt = 0; nt < 8; nt++) {
            oacc[nt][0] *= f0; oacc[nt][1] *= f0;
            oacc[nt][2] *= f1; oacc[nt][3] *= f1;
        }
        __syncwarp();

        #pragma unroll
        for (int ks = 0; ks < 8; ks++) {
            uint32_t af[4];
            af[0] = Ps[prow    ][ks*8 + c    ];
            af[1] = Ps[prow + 8][ks*8 + c    ];
            af[2] = Ps[prow    ][ks*8 + c + 4];
            af[3] = Ps[prow + 8][ks*8 + c + 4];
            #pragma unroll
            for (int nt = 0; nt < 8; nt++) {
                uint32_t b0 = Vs[ks*8 + c    ][nt*8 + r];
                uint32_t b1 = Vs[ks*8 + c + 4][nt*8 + r];
                mma_tf32(oacc[nt], af, b0, b1);
            }
        }
        __syncwarp();
    }

    float il0 = 1.f / l0, il1 = 1.f / l1;
    const int grow = b*TT + q0 + warp*16 + r;
    float* op0 = out + (size_t)grow * CC + h*HS;
    float* op1 = op0 + (size_t)8 * CC;
    #pragma unroll
    for (int nt = 0; nt < 8; nt++) {
        int col = nt*8 + 2*c;
        *(float2*)(op0 + col) = make_float2(oacc[nt][0]*il0, oacc[nt][1]*il0);
        *(float2*)(op1 + col) = make_float2(oacc[nt][2]*il1, oacc[nt][3]*il1);
    }
}

// ---------------- launch -----------------------------------------------
extern "C" void kernel_launch(void* const* d_in, const int* in_sizes, int n_in,
                              void* d_out, int out_size)
{
    const float* x      = (const float*)d_in[0];
    const float* Wq     = (const float*)d_in[1];
    const float* bq     = (const float*)d_in[2];
    const float* Wk     = (const float*)d_in[3];
    const float* bk     = (const float*)d_in[4];
    const float* Wv     = (const float*)d_in[5];
    const float* bv     = (const float*)d_in[6];
    const float* Wo     = (const float*)d_in[7];
    const float* bo     = (const float*)d_in[8];
    const float* W1     = (const float*)d_in[9];
    const float* b1     = (const float*)d_in[10];
    const float* W2     = (const float*)d_in[11];
    const float* b2     = (const float*)d_in[12];
    const float* gamma1 = (const float*)d_in[13];
    const float* beta1  = (const float*)d_in[14];
    const float* gamma2 = (const float*)d_in[15];
    const float* beta2  = (const float*)d_in[16];
    float* out = (float*)d_out;

    float *p_h, *p_x1, *p_attn, *p_qkv, *p_wqkv, *p_bqkv, *p_mid, *p_mean, *p_inv;
    cudaGetSymbolAddress((void**)&p_h,    g_h);
    cudaGetSymbolAddress((void**)&p_x1,   g_x1);
    cudaGetSymbolAddress((void**)&p_attn, g_attn);
    cudaGetSymbolAddress((void**)&p_qkv,  g_qkv);
    cudaGetSymbolAddress((void**)&p_wqkv, g_wqkv);
    cudaGetSymbolAddress((void**)&p_bqkv, g_bqkv);
    cudaGetSymbolAddress((void**)&p_mid,  g_mid);
    cudaGetSymbolAddress((void**)&p_mean, g_mean);
    cudaGetSymbolAddress((void**)&p_inv,  g_inv);

    dim3 lnb(32, 8);
    dim3 lng(CC/32, BB);
    const int elemBlocks = (MM*CC + 255)/256;

    // 1) LN1
    ln_stats<<<lng, lnb>>>(x, p_mean, p_inv);
    ln_apply<<<elemBlocks, 256>>>(x, p_mean, p_inv, gamma1, beta1, p_h);

    // 2) pack QKV weights + fused QKV GEMM -> g_qkv [4096, 3072]
    pack_qkv<<<4096, 256>>>(Wq, Wk, Wv, bq, bk, bv, p_wqkv, p_bqkv);
    mma_gemm<false,false><<<dim3(3*CC/128, MM/128), 256>>>(p_h, p_wqkv, p_bqkv, nullptr,
                                                           p_qkv, MM, 3*CC, CC);

    // 3) flash attention -> g_attn [4096, 1024]
    flash_mma<<<dim3(TT/64, HH, BB), 128>>>(p_qkv, p_attn);

    // 4) output projection + residual -> g_x1
    mma_gemm<false,true><<<dim3(CC/128, MM/128), 256>>>(p_attn, Wo, bo, x,
                                                        p_x1, MM, CC, CC);

    // 5) LN2
    ln_stats<<<lng, lnb>>>(p_x1, p_mean, p_inv);
    ln_apply<<<elemBlocks, 256>>>(p_x1, p_mean, p_inv, gamma2, beta2, p_h);

    // 6) FFN
    mma_gemm<true,false><<<dim3(4*CC/128, MM/128), 256>>>(p_h, W1, b1, nullptr,
                                                          p_mid, MM, 4*CC, CC);
    mma_gemm<false,true><<<dim3(CC/128, MM/128), 256>>>(p_mid, W2, b2, p_x1,
                                                        out, MM, CC, 4*CC);
}